// round 9
// baseline (speedup 1.0000x reference)
#include <cuda_runtime.h>
#include <cuda_bf16.h>
#include <cstdint>

// Problem constants (fixed by the dataset): B=8, S=4096, D=1024, fp32.
#define BB 8
#define SS 4096
#define DD 1024

// ---------------------------------------------------------------------------
// Fused kernel: inline mask-prefix + row gather.
//
// Math note (why the affine scan collapses): at a boundary j, a=0,b=cur so
// y_j = cur_j exactly; within a segment cum (hence cur) is constant and the
// EMA y = (1-p) y + p cur sits at its fixed point y = cur from the segment's
// first element on. Before the first boundary, cur = 0 and b = 0, so y = 0.
// Therefore y[b,j,:] = cum>0 ? compressed[b, cum-1, :] : 0  -- a pure gather.
//
// Mask layout: int32 words, one per element (established experimentally:
// byte interpretation fails with rel_err 1.41, int32 passes at 1.9e-8).
//
// A/B under test: default write-back stores instead of __stcs. DRAM traffic
// is ~93% output writes; L2 protection for reads buys nothing (~11 MB), while
// evict-first streaming may force early partial-sector writebacks and degrade
// DRAM write efficiency. Single-variable A/B vs the measured 31.2us kernel.
// ---------------------------------------------------------------------------
__global__ __launch_bounds__(256)
void dechunk_fused_kernel(const float* __restrict__ comp,
                          const unsigned int* __restrict__ mask32,
                          float* __restrict__ out)
{
    const int blk  = blockIdx.x;            // 0..4095
    const int b    = blk >> 9;              // 512 blocks per batch
    const int j0   = (blk & 511) << 3;      // first row of this block's window
    const int tid  = threadIdx.x;
    const int lane = tid & 31;
    const int warp = tid >> 5;

    __shared__ int          warp_sums[8];
    __shared__ int          idx_sh[8];
    __shared__ unsigned int win[8];

    const unsigned int* m = mask32 + b * SS;

    // ---- Phase A: prefix count of boundaries in [0, j0), plus window bits --
    if (tid < 8) win[tid] = m[j0 + tid];

    int s = 0;
    for (int i = tid; i < j0; i += 256)     // <= 16 iterations, coalesced
        s += (m[i] != 0u) ? 1 : 0;

#pragma unroll
    for (int o = 16; o > 0; o >>= 1)
        s += __shfl_down_sync(0xFFFFFFFFu, s, o);
    if (lane == 0) warp_sums[warp] = s;
    __syncthreads();

    if (tid == 0) {
        int cum = 0;
#pragma unroll
        for (int i = 0; i < 8; ++i) cum += warp_sums[i];
#pragma unroll
        for (int i = 0; i < 8; ++i) {
            cum += (win[i] != 0u) ? 1 : 0;
            idx_sh[i] = cum - 1;            // -1 when no boundary seen yet
        }
    }
    __syncthreads();

    // ---- Phase B: row gather, MLP=8 loads, default write-back stores ------
    const int idx = idx_sh[warp];
    const int row = blk * 8 + warp;         // b*SS + j0 + warp

    float4* dst = reinterpret_cast<float4*>(out) + (long long)row * 256;

    if (idx < 0) {
        const float4 z = make_float4(0.f, 0.f, 0.f, 0.f);
#pragma unroll
        for (int i = 0; i < 8; ++i)
            dst[lane + 32 * i] = z;
    } else {
        const float4* src = reinterpret_cast<const float4*>(comp)
                          + ((long long)(b * SS + idx)) * 256;
        float4 v[8];
#pragma unroll
        for (int i = 0; i < 8; ++i)         // 8 independent loads -> MLP=8
            v[i] = __ldg(&src[lane + 32 * i]);
#pragma unroll
        for (int i = 0; i < 8; ++i)
            dst[lane + 32 * i] = v[i];
    }
}

// ---------------------------------------------------------------------------
// Launch. Inputs identified by element count (order-proof):
//   compressed_states fp32 [8,4096,1024] -> 33554432 elems
//   boundary_prob     fp32 [8,4096,2]    ->    65536 elems (unused)
//   boundary_mask     bool [8,4096]      ->    32768 elems (int32 words)
// Output: fp32 [8,4096,1024]
// ---------------------------------------------------------------------------
extern "C" void kernel_launch(void* const* d_in, const int* in_sizes, int n_in,
                              void* d_out, int out_size)
{
    const void* comp_p = d_in[0];
    const void* mask_p = (n_in > 2) ? d_in[2] : d_in[0];

    for (int i = 0; i < n_in; ++i) {
        if (in_sizes[i] == BB * SS * DD) comp_p = d_in[i];
        else if (in_sizes[i] == BB * SS) mask_p = d_in[i];
    }

    dechunk_fused_kernel<<<(BB * SS) / 8, 256>>>(
        (const float*)comp_p, (const unsigned int*)mask_p, (float*)d_out);
}